// round 16
// baseline (speedup 1.0000x reference)
#include <cuda_runtime.h>
#include <cuda_bf16.h>
#include <cuda_fp16.h>
#include <cstddef>
#include <cstdint>

// Problem dims (fixed by the benchmark)
#define BB 128
#define TT 512
#define DD 512
#define UU 1024
#define GG 4096   // 4*U
#define OO 512
#define MM (BB * TT)   // 65536

#define NBLK 128        // persistent CTAs for scan

// ---------------- scratch (static device globals; no runtime allocation) ----
__device__ float g_xz[(size_t)MM * GG];        // [B*T][4U]
__device__ unsigned g_bar;                     // grid barrier counter

__device__ __half g_ax[(size_t)MM * DD];       // x  -> [M][512] fp16
__device__ __half g_bk[(size_t)GG * DD];       // kernel^T -> [4096][512] fp16
__device__ __half g_bw[(size_t)OO * UU];       // Wd^T -> [512][1024] fp16
__device__ __half g_hf[(size_t)(TT + 1) * BB * UU];  // fp16 h; slot 0 = h0

// ---------------- helpers ----------------------------------------------------
__device__ __forceinline__ float sigmoidf_(float x) { return 1.0f / (1.0f + __expf(-x)); }

__device__ __forceinline__ void cp16s(uint32_t daddr, const void* g) {
    asm volatile("cp.async.cg.shared.global [%0], [%1], 16;" :: "r"(daddr), "l"(g));
}
#define CP_COMMIT()  asm volatile("cp.async.commit_group;")
#define CP_WAIT(N)   asm volatile("cp.async.wait_group %0;" :: "n"(N))

__device__ __forceinline__ void ldsm_x4(uint32_t &r0, uint32_t &r1,
                                        uint32_t &r2, uint32_t &r3, uint32_t a) {
    asm volatile("ldmatrix.sync.aligned.m8n8.x4.shared.b16 {%0,%1,%2,%3}, [%4];"
                 : "=r"(r0), "=r"(r1), "=r"(r2), "=r"(r3) : "r"(a));
}
__device__ __forceinline__ void mma16816h(float* d, const uint32_t* a,
                                          const uint32_t* b) {
    asm volatile(
        "mma.sync.aligned.m16n8k16.row.col.f32.f16.f16.f32 "
        "{%0,%1,%2,%3}, {%4,%5,%6,%7}, {%8,%9}, {%0,%1,%2,%3};"
        : "+f"(d[0]), "+f"(d[1]), "+f"(d[2]), "+f"(d[3])
        : "r"(a[0]), "r"(a[1]), "r"(a[2]), "r"(a[3]), "r"(b[0]), "r"(b[1]));
}
__device__ __forceinline__ uint32_t swz(uint32_t o) { return o ^ ((o >> 3) & 0x70); }
__device__ __forceinline__ uint32_t packhf(__half a, __half b) {
    uint16_t x = *(uint16_t*)&a, y = *(uint16_t*)&b;
    return (uint32_t)x | ((uint32_t)y << 16);
}
__device__ __forceinline__ uint4 tohalf8(const float* vs) {
    __half h[8];
#pragma unroll
    for (int j = 0; j < 8; j++) h[j] = __float2half_rn(vs[j]);
    return make_uint4(packhf(h[0], h[1]), packhf(h[2], h[3]),
                      packhf(h[4], h[5]), packhf(h[6], h[7]));
}

// ---------------- prep kernels (vectorized: 8 elems/thread) ------------------
__global__ __launch_bounds__(256) void init_state(const float* __restrict__ h0) {
    int i = blockIdx.x * 256 + threadIdx.x;   // over BB*UU/8 = 16384
    float vs[8];
    *(float4*)&vs[0] = *(const float4*)&h0[i * 8];
    *(float4*)&vs[4] = *(const float4*)&h0[i * 8 + 4];
    *(uint4*)&g_hf[i * 8] = tohalf8(vs);       // slot 0 = h0
    if (i == 0) g_bar = 0u;
}

// x [M][512] fp32 -> g_ax [M][512] fp16
__global__ __launch_bounds__(256) void split_x(const float* __restrict__ in) {
    size_t i = (size_t)blockIdx.x * 256 + threadIdx.x;   // M*DD/8
    size_t e0 = i * 8;
    float vs[8];
    *(float4*)&vs[0] = *(const float4*)&in[e0];
    *(float4*)&vs[4] = *(const float4*)&in[e0 + 4];
    *(uint4*)&g_ax[e0] = tohalf8(vs);
}

// kernel [512][4096] fp32 -> g_bk [4096][512] fp16 (transposed)
__global__ __launch_bounds__(256) void split_k(const float* __restrict__ in) {
    size_t i = (size_t)blockIdx.x * 256 + threadIdx.x;   // GG * DD/8
    int n = (int)(i & (GG - 1));
    int k0 = (int)(i >> 12) * 8;
    float vs[8];
#pragma unroll
    for (int j = 0; j < 8; j++)
        vs[j] = in[(size_t)(k0 + j) * GG + n];
    *(uint4*)&g_bk[(size_t)n * DD + k0] = tohalf8(vs);
}

// Wd [1024][512] fp32 -> g_bw [512][1024] fp16 (transposed)
__global__ __launch_bounds__(256) void split_w(const float* __restrict__ in) {
    size_t i = (size_t)blockIdx.x * 256 + threadIdx.x;   // OO * UU/8
    int n = (int)(i & (OO - 1));
    int k0 = (int)(i >> 9) * 8;
    float vs[8];
#pragma unroll
    for (int j = 0; j < 8; j++)
        vs[j] = in[(size_t)(k0 + j) * OO + n];
    *(uint4*)&g_bw[(size_t)n * UU + k0] = tohalf8(vs);
}

// ---------------- mma.sync fp16 GEMM (128x256 tile, warp 64x64) -------------
#define GEM_BUF 49152
#define MMASM (2 * GEM_BUF)

__global__ __launch_bounds__(256, 1) void mma_gemm(
    const __half* __restrict__ A2, const __half* __restrict__ B2,
    const float* __restrict__ bias, float* __restrict__ C, int K2, int N) {
    extern __shared__ char smc[];
    const uint32_t sbase = (uint32_t)__cvta_generic_to_shared(smc);
    const int tid = threadIdx.x;
    const int wid = tid >> 5, lid = tid & 31;
    const int n0 = blockIdx.x * 256;
    const int m0 = blockIdx.y * 128;
    const int wm = (wid & 1) * 64;
    const int wn = (wid >> 1) * 64;
    const int nch = K2 / 64;

    float d[4][8][4];
#pragma unroll
    for (int i = 0; i < 4; i++)
#pragma unroll
        for (int j = 0; j < 8; j++)
#pragma unroll
            for (int q = 0; q < 4; q++) d[i][j][q] = 0.0f;

    auto load_chunk = [&](int buf, int k0) {
        uint32_t ab = sbase + buf * GEM_BUF;
        uint32_t bb = ab + 16384;
#pragma unroll
        for (int i = 0; i < 4; i++) {           // A: 128 rows x 64k
            int e = tid + i * 256;
            int rr = e >> 3, c8 = e & 7;
            uint32_t off = swz((uint32_t)(rr * 128 + c8 * 16));
            cp16s(ab + off, A2 + (size_t)(m0 + rr) * K2 + k0 + c8 * 8);
        }
#pragma unroll
        for (int i = 0; i < 8; i++) {           // B: 256 rows x 64k
            int e = tid + i * 256;
            int rr = e >> 3, c8 = e & 7;
            uint32_t off = swz((uint32_t)(rr * 128 + c8 * 16));
            cp16s(bb + off, B2 + (size_t)(n0 + rr) * K2 + k0 + c8 * 8);
        }
    };

    load_chunk(0, 0);
    CP_COMMIT();

    int buf = 0;
    for (int c = 0; c < nch; c++) {
        if (c + 1 < nch) {
            load_chunk(buf ^ 1, (c + 1) * 64);
            CP_COMMIT();
            CP_WAIT(1);
        } else {
            CP_WAIT(0);
        }
        __syncthreads();

        const uint32_t ab = sbase + buf * GEM_BUF;
        const uint32_t bb = ab + 16384;
#pragma unroll
        for (int kk = 0; kk < 64; kk += 16) {
            uint32_t af[4][4];
#pragma unroll
            for (int mi = 0; mi < 4; mi++) {
                uint32_t off = (uint32_t)((wm + mi * 16 + (lid & 15)) * 128
                                          + kk * 2 + (lid >> 4) * 16);
                ldsm_x4(af[mi][0], af[mi][1], af[mi][2], af[mi][3], ab + swz(off));
            }
            uint32_t bf_[8][2];
#pragma unroll
            for (int ni = 0; ni < 4; ni++) {
                int sub = lid >> 3;
                uint32_t off = (uint32_t)((wn + ni * 16 + ((sub >> 1) & 1) * 8
                                           + (lid & 7)) * 128
                                          + kk * 2 + (sub & 1) * 16);
                ldsm_x4(bf_[ni * 2][0], bf_[ni * 2][1],
                        bf_[ni * 2 + 1][0], bf_[ni * 2 + 1][1], bb + swz(off));
            }
#pragma unroll
            for (int mi = 0; mi < 4; mi++)
#pragma unroll
                for (int nf = 0; nf < 8; nf++)
                    mma16816h(d[mi][nf], af[mi], bf_[nf]);
        }
        __syncthreads();
        buf ^= 1;
    }

    const int lr = lid >> 2;
    const int lc = (lid & 3) * 2;
#pragma unroll
    for (int mi = 0; mi < 4; mi++) {
#pragma unroll
        for (int nf = 0; nf < 8; nf++) {
            int col = n0 + wn + nf * 8 + lc;
            float b0 = bias[col], b1 = bias[col + 1];
            int row0 = m0 + wm + mi * 16 + lr;
            float2 v0 = make_float2(d[mi][nf][0] + b0, d[mi][nf][1] + b1);
            float2 v1 = make_float2(d[mi][nf][2] + b0, d[mi][nf][3] + b1);
            *(float2*)&C[(size_t)row0 * N + col] = v0;
            *(float2*)&C[(size_t)(row0 + 8) * N + col] = v1;
        }
    }
}

// ---------------- projection GEMM (128x256 tile): out = hs @ Wd + bd ---------
__global__ __launch_bounds__(256, 1) void proj_gemm(
    const __half* __restrict__ hf, const __half* __restrict__ B2,
    const float* __restrict__ bias, float* __restrict__ C) {
    extern __shared__ char smc[];
    const uint32_t sbase = (uint32_t)__cvta_generic_to_shared(smc);
    const int tid = threadIdx.x;
    const int wid = tid >> 5, lid = tid & 31;
    const int n0 = blockIdx.x * 256;
    const int m0 = blockIdx.y * 128;
    const int wm = (wid & 1) * 64;
    const int wn = (wid >> 1) * 64;
    const int nch = 16;   // 1024 / 64

    float d[4][8][4];
#pragma unroll
    for (int i = 0; i < 4; i++)
#pragma unroll
        for (int j = 0; j < 8; j++)
#pragma unroll
            for (int q = 0; q < 4; q++) d[i][j][q] = 0.0f;

    auto load_chunk = [&](int buf, int ck) {
        uint32_t ab = sbase + buf * GEM_BUF;
        uint32_t bb = ab + 16384;
        const int kcol = ck * 64;
#pragma unroll
        for (int i = 0; i < 4; i++) {
            int e = tid + i * 256;
            int rr = e >> 3, c8 = e & 7;
            uint32_t off = swz((uint32_t)(rr * 128 + c8 * 16));
            int m = m0 + rr;
            int b = m >> 9, t = m & 511;           // m = b*TT + t
            cp16s(ab + off, hf + ((size_t)(t + 1) * BB + b) * UU + kcol + c8 * 8);
        }
#pragma unroll
        for (int i = 0; i < 8; i++) {
            int e = tid + i * 256;
            int rr = e >> 3, c8 = e & 7;
            uint32_t off = swz((uint32_t)(rr * 128 + c8 * 16));
            cp16s(bb + off, B2 + (size_t)(n0 + rr) * UU + kcol + c8 * 8);
        }
    };

    load_chunk(0, 0);
    CP_COMMIT();

    int buf = 0;
    for (int c = 0; c < nch; c++) {
        if (c + 1 < nch) {
            load_chunk(buf ^ 1, c + 1);
            CP_COMMIT();
            CP_WAIT(1);
        } else {
            CP_WAIT(0);
        }
        __syncthreads();

        const uint32_t ab = sbase + buf * GEM_BUF;
        const uint32_t bb = ab + 16384;
#pragma unroll
        for (int kk = 0; kk < 64; kk += 16) {
            uint32_t af[4][4];
#pragma unroll
            for (int mi = 0; mi < 4; mi++) {
                uint32_t off = (uint32_t)((wm + mi * 16 + (lid & 15)) * 128
                                          + kk * 2 + (lid >> 4) * 16);
                ldsm_x4(af[mi][0], af[mi][1], af[mi][2], af[mi][3], ab + swz(off));
            }
            uint32_t bf_[8][2];
#pragma unroll
            for (int ni = 0; ni < 4; ni++) {
                int sub = lid >> 3;
                uint32_t off = (uint32_t)((wn + ni * 16 + ((sub >> 1) & 1) * 8
                                           + (lid & 7)) * 128
                                          + kk * 2 + (sub & 1) * 16);
                ldsm_x4(bf_[ni * 2][0], bf_[ni * 2][1],
                        bf_[ni * 2 + 1][0], bf_[ni * 2 + 1][1], bb + swz(off));
            }
#pragma unroll
            for (int mi = 0; mi < 4; mi++)
#pragma unroll
                for (int nf = 0; nf < 8; nf++)
                    mma16816h(d[mi][nf], af[mi], bf_[nf]);
        }
        __syncthreads();
        buf ^= 1;
    }

    const int lr = lid >> 2;
    const int lc = (lid & 3) * 2;
#pragma unroll
    for (int mi = 0; mi < 4; mi++) {
#pragma unroll
        for (int nf = 0; nf < 8; nf++) {
            int col = n0 + wn + nf * 8 + lc;
            float b0 = bias[col], b1 = bias[col + 1];
            int row0 = m0 + wm + mi * 16 + lr;
            float2 v0 = make_float2(d[mi][nf][0] + b0, d[mi][nf][1] + b1);
            float2 v1 = make_float2(d[mi][nf][2] + b0, d[mi][nf][3] + b1);
            *(float2*)&C[(size_t)row0 * OO + col] = v0;
            *(float2*)&C[(size_t)(row0 + 8) * OO + col] = v1;
        }
    }
}

// ---------------- persistent MMA LSTM scan (fp16, M64 x N64 tiles) ----------
// 128 CTAs, 256 threads. CTA g: batch half mh=g&1 (64 rows), col group
// cg=g>>1: hidden cols [16cg,16cg+16) x 4 gates, interleaved n = j*4 + gate.
// Halves per-step A L2 traffic (16 MB/step) vs M128xN32. R smem 128 KB.
// Warps: wm=(wid&3)*16 (M slice), wn=(wid>>2)*32 (N half). Gate update via
// shfl_xor(1) (complementary gate pairs) + shfl_xor(2) (h store packing).
#define SC_A  131072                 // R occupies [0, 128K)
#define SCANSM (SC_A + 2 * 16384)    // 163840

__global__ __launch_bounds__(256, 1) void lstm_scan_mma(
    const float* __restrict__ R, const float* __restrict__ c0in) {
    extern __shared__ char smc[];
    const uint32_t sb = (uint32_t)__cvta_generic_to_shared(smc);
    const int tid = threadIdx.x;
    const int wid = tid >> 5, lid = tid & 31;
    const int mh = blockIdx.x & 1;
    const int cg = blockIdx.x >> 1;
    const int u0g = cg * 16;
    const int wm = (wid & 3) * 16;
    const int wn = (wid >> 2) * 32;

    // ---- one-time: R slice [64 n x 1024 k] -> smem fp16, 16 x 8KB sub-tiles
    for (int e = tid; e < 64 * UU; e += 256) {
        int n = e & 63, k = e >> 6;
        int g = n & 3, j = n >> 2;
        float v = R[(size_t)k * GG + g * UU + u0g + j];
        uint32_t off = (uint32_t)((k >> 6) * 8192)
                     + swz((uint32_t)(n * 128 + (k & 63) * 2));
        *(__half*)(smc + off) = __float2half_rn(v);
    }

    // lane constants
    const int lr = lid >> 2;
    const int bit0 = lid & 1;           // gate-half / row-half owner
    const int bit1 = (lid >> 1) & 1;    // j parity
    const int b = mh * 64 + wm + lr + bit0 * 8;
    const int ubase = u0g + (wn >> 2) + bit1;   // u of combo nf: ubase + nf*2

    float creg[4];
#pragma unroll
    for (int nf = 0; nf < 4; nf++)
        creg[nf] = c0in[(size_t)b * UU + ubase + nf * 2];

    __syncthreads();

    for (int t = 0; t < TT; t++) {
        const __half* abase = g_hf + (size_t)t * BB * UU;   // h_{t-1}

        // one chunk = 64 rows x 128 K cols: two 8KB sub-tiles
        auto loadA = [&](int buf, int ck) {
            uint32_t ah = sb + SC_A + buf * 16384;
#pragma unroll
            for (int i = 0; i < 4; i++) {
                int e = tid + i * 256;              // 0..1023
                int s = e >> 9;                     // sub-tile 0/1
                int e2 = e & 511;
                int rr = e2 >> 3, c8 = e2 & 7;
                uint32_t off = (uint32_t)(s * 8192)
                             + swz((uint32_t)(rr * 128 + c8 * 16));
                cp16s(ah + off, abase + (size_t)(mh * 64 + rr) * UU
                                + ck * 128 + s * 64 + c8 * 8);
            }
        };

        loadA(0, 0);
        CP_COMMIT();

        // prefetch xz for this step (hidden under MMA)
        float xzv[4][4];
#pragma unroll
        for (int nf = 0; nf < 4; nf++) {
            const float* p = &g_xz[((size_t)b * TT + t) * GG + ubase + nf * 2];
#pragma unroll
            for (int g = 0; g < 4; g++) xzv[nf][g] = p[(size_t)g * UU];
        }

        float d[4][4];
#pragma unroll
        for (int f = 0; f < 4; f++)
#pragma unroll
            for (int q = 0; q < 4; q++) d[f][q] = 0.0f;

        int buf = 0;
        for (int ck = 0; ck < 8; ck++) {
            if (ck + 1 < 8) {
                loadA(buf ^ 1, ck + 1);
                CP_COMMIT();
                CP_WAIT(1);
            } else {
                CP_WAIT(0);
            }
            __syncthreads();

            const uint32_t ah = sb + SC_A + buf * 16384;
#pragma unroll
            for (int s = 0; s < 2; s++) {
                const uint32_t ahs = ah + s * 8192;
                const uint32_t rh = sb + (ck * 2 + s) * 8192;
#pragma unroll
                for (int kk = 0; kk < 64; kk += 16) {
                    uint32_t offA = swz((uint32_t)((wm + (lid & 15)) * 128
                                                   + kk * 2 + (lid >> 4) * 16));
                    uint32_t af[4];
                    ldsm_x4(af[0], af[1], af[2], af[3], ahs + offA);

                    uint32_t bh[4][2];
#pragma unroll
                    for (int ni = 0; ni < 2; ni++) {
                        int sub = lid >> 3;
                        uint32_t offB = swz((uint32_t)((wn + ni * 16 + ((sub >> 1) & 1) * 8
                                                        + (lid & 7)) * 128
                                                       + kk * 2 + (sub & 1) * 16));
                        ldsm_x4(bh[ni * 2][0], bh[ni * 2][1],
                                bh[ni * 2 + 1][0], bh[ni * 2 + 1][1], rh + offB);
                    }
#pragma unroll
                    for (int f = 0; f < 4; f++)
                        mma16816h(d[f], af, bh[f]);
                }
            }
            __syncthreads();
            buf ^= 1;
        }

        // ---- gate exchange: partner lane (lid^1) holds complementary gates
        float rec_[4][4];
#pragma unroll
        for (int f = 0; f < 4; f++)
#pragma unroll
            for (int q = 0; q < 4; q++)
                rec_[f][q] = __shfl_xor_sync(0xffffffffu, d[f][q], 1);

        float hn[4];
#pragma unroll
        for (int nf = 0; nf < 4; nf++) {
            float zi, zf, zg, zo;
            if (bit0 == 0) {        // own cols = gates (i,f), row +0
                zi = d[nf][0];  zf = d[nf][1];
                zg = rec_[nf][0]; zo = rec_[nf][1];
            } else {                // own cols = gates (g,o), row +8
                zi = rec_[nf][2]; zf = rec_[nf][3];
                zg = d[nf][2];  zo = d[nf][3];
            }
            zi += xzv[nf][0]; zf += xzv[nf][1];
            zg += xzv[nf][2]; zo += xzv[nf][3];
            float ig = sigmoidf_(zi);
            float fg = sigmoidf_(zf);
            float og = sigmoidf_(zo);
            float gg = tanhf(zg);
            float cn = fg * creg[nf] + ig * gg;
            creg[nf] = cn;
            hn[nf] = og * tanhf(cn);
        }

        // ---- h store: lane^2 holds u+1 for same row; pack into STG.32
#pragma unroll
        for (int nf = 0; nf < 4; nf++) {
            float ph = __shfl_xor_sync(0xffffffffu, hn[nf], 2);
            if (bit1 == 0) {
                int u = ubase + nf * 2;        // even
                *(uint32_t*)&g_hf[((size_t)(t + 1) * BB + b) * UU + u] =
                    packhf(__float2half_rn(hn[nf]), __float2half_rn(ph));
            }
        }

        // grid barrier
        __syncthreads();
        if (tid == 0) {
            __threadfence();
            atomicAdd(&g_bar, 1u);
            unsigned target = (unsigned)(t + 1) * NBLK;
            unsigned v;
            do {
                asm volatile("ld.global.acquire.gpu.u32 %0, [%1];"
                             : "=r"(v) : "l"(&g_bar) : "memory");
                if (v < target) __nanosleep(32);
            } while (v < target);
        }
        __syncthreads();
    }
}

// ---------------- host launcher --------------------------------------------
extern "C" void kernel_launch(void* const* d_in, const int* in_sizes, int n_in,
                              void* d_out, int out_size) {
    const float* x      = (const float*)d_in[0];
    const float* h0     = (const float*)d_in[1];
    const float* c0in   = (const float*)d_in[2];
    const float* kernel = (const float*)d_in[3];
    const float* rec    = (const float*)d_in[4];
    const float* bias   = (const float*)d_in[5];
    const float* Wd     = (const float*)d_in[6];
    const float* bd     = (const float*)d_in[7];
    float* out = (float*)d_out;

    void *p_xz, *p_ax, *p_bk, *p_bw, *p_hf;
    cudaGetSymbolAddress(&p_xz, g_xz);
    cudaGetSymbolAddress(&p_ax, g_ax);
    cudaGetSymbolAddress(&p_bk, g_bk);
    cudaGetSymbolAddress(&p_bw, g_bw);
    cudaGetSymbolAddress(&p_hf, g_hf);

    static bool attr_done = false;
    if (!attr_done) {
        cudaFuncSetAttribute(lstm_scan_mma,
                             cudaFuncAttributeMaxDynamicSharedMemorySize, SCANSM);
        cudaFuncSetAttribute(mma_gemm,
                             cudaFuncAttributeMaxDynamicSharedMemorySize, MMASM);
        cudaFuncSetAttribute(proj_gemm,
                             cudaFuncAttributeMaxDynamicSharedMemorySize, MMASM);
        attr_done = true;
    }

    // 1) state init + operand converts (vectorized)
    init_state<<<(BB * UU / 8) / 256, 256>>>(h0);
    split_x<<<(int)((size_t)MM * DD / 8 / 256), 256>>>(x);
    split_k<<<(int)((size_t)DD * GG / 8 / 256), 256>>>(kernel);
    split_w<<<(int)((size_t)UU * OO / 8 / 256), 256>>>(Wd);

    // 2) xz = x @ kernel + bias  (fp16 1-term; M=65536, N=4096, K=512)
    {
        dim3 grid(GG / 256, MM / 128);
        mma_gemm<<<grid, 256, MMASM>>>((const __half*)p_ax, (const __half*)p_bk,
                                       bias, (float*)p_xz, DD, GG);
    }

    // 3) persistent MMA LSTM scan (M64xN64 tiles, writes g_hf)
    lstm_scan_mma<<<NBLK, 256, SCANSM>>>(rec, c0in);

    // 4) out = hs @ Wd + bd  (fp16 1-term from g_hf; M=65536, N=512, K=1024)
    {
        dim3 grid(OO / 256, MM / 128);
        proj_gemm<<<grid, 256, MMASM>>>((const __half*)p_hf, (const __half*)p_bw,
                                        bd, out);
    }
}

// round 17
// speedup vs baseline: 1.7228x; 1.7228x over previous
#include <cuda_runtime.h>
#include <cuda_bf16.h>
#include <cuda_fp16.h>
#include <cstddef>
#include <cstdint>

// Problem dims (fixed by the benchmark)
#define BB 128
#define TT 512
#define DD 512
#define UU 1024
#define GG 4096   // 4*U
#define OO 512
#define MM (BB * TT)   // 65536

#define NBLK 128        // persistent CTAs for scan

// ---------------- scratch (static device globals; no runtime allocation) ----
__device__ float g_xz[(size_t)MM * GG];        // [B*T][4U]
__device__ unsigned g_bar;                     // grid barrier counter

__device__ __half g_ax[(size_t)MM * DD];       // x  -> [M][512] fp16
__device__ __half g_bk[(size_t)GG * DD];       // kernel^T -> [4096][512] fp16
__device__ __half g_bw[(size_t)OO * UU];       // Wd^T -> [512][1024] fp16
__device__ __half g_hf[(size_t)(TT + 1) * BB * UU];  // fp16 h; slot 0 = h0

// ---------------- helpers ----------------------------------------------------
__device__ __forceinline__ float sigmoidf_(float x) { return 1.0f / (1.0f + __expf(-x)); }

__device__ __forceinline__ void cp16s(uint32_t daddr, const void* g) {
    asm volatile("cp.async.cg.shared.global [%0], [%1], 16;" :: "r"(daddr), "l"(g));
}
#define CP_COMMIT()  asm volatile("cp.async.commit_group;")
#define CP_WAIT(N)   asm volatile("cp.async.wait_group %0;" :: "n"(N))

__device__ __forceinline__ void ldsm_x4(uint32_t &r0, uint32_t &r1,
                                        uint32_t &r2, uint32_t &r3, uint32_t a) {
    asm volatile("ldmatrix.sync.aligned.m8n8.x4.shared.b16 {%0,%1,%2,%3}, [%4];"
                 : "=r"(r0), "=r"(r1), "=r"(r2), "=r"(r3) : "r"(a));
}
__device__ __forceinline__ void mma16816h(float* d, const uint32_t* a,
                                          const uint32_t* b) {
    asm volatile(
        "mma.sync.aligned.m16n8k16.row.col.f32.f16.f16.f32 "
        "{%0,%1,%2,%3}, {%4,%5,%6,%7}, {%8,%9}, {%0,%1,%2,%3};"
        : "+f"(d[0]), "+f"(d[1]), "+f"(d[2]), "+f"(d[3])
        : "r"(a[0]), "r"(a[1]), "r"(a[2]), "r"(a[3]), "r"(b[0]), "r"(b[1]));
}
__device__ __forceinline__ uint32_t swz(uint32_t o) { return o ^ ((o >> 3) & 0x70); }
__device__ __forceinline__ uint32_t packhf(__half a, __half b) {
    uint16_t x = *(uint16_t*)&a, y = *(uint16_t*)&b;
    return (uint32_t)x | ((uint32_t)y << 16);
}
__device__ __forceinline__ uint4 tohalf8(const float* vs) {
    __half h[8];
#pragma unroll
    for (int j = 0; j < 8; j++) h[j] = __float2half_rn(vs[j]);
    return make_uint4(packhf(h[0], h[1]), packhf(h[2], h[3]),
                      packhf(h[4], h[5]), packhf(h[6], h[7]));
}

// ---------------- prep kernels (vectorized: 8 elems/thread) ------------------
__global__ __launch_bounds__(256) void init_state(const float* __restrict__ h0) {
    int i = blockIdx.x * 256 + threadIdx.x;   // over BB*UU/8 = 16384
    float vs[8];
    *(float4*)&vs[0] = *(const float4*)&h0[i * 8];
    *(float4*)&vs[4] = *(const float4*)&h0[i * 8 + 4];
    *(uint4*)&g_hf[i * 8] = tohalf8(vs);       // slot 0 = h0
    if (i == 0) g_bar = 0u;
}

// x [M][512] fp32 -> g_ax [M][512] fp16
__global__ __launch_bounds__(256) void split_x(const float* __restrict__ in) {
    size_t i = (size_t)blockIdx.x * 256 + threadIdx.x;   // M*DD/8
    size_t e0 = i * 8;
    float vs[8];
    *(float4*)&vs[0] = *(const float4*)&in[e0];
    *(float4*)&vs[4] = *(const float4*)&in[e0 + 4];
    *(uint4*)&g_ax[e0] = tohalf8(vs);
}

// kernel [512][4096] fp32 -> g_bk [4096][512] fp16 (transposed)
__global__ __launch_bounds__(256) void split_k(const float* __restrict__ in) {
    size_t i = (size_t)blockIdx.x * 256 + threadIdx.x;   // GG * DD/8
    int n = (int)(i & (GG - 1));
    int k0 = (int)(i >> 12) * 8;
    float vs[8];
#pragma unroll
    for (int j = 0; j < 8; j++)
        vs[j] = in[(size_t)(k0 + j) * GG + n];
    *(uint4*)&g_bk[(size_t)n * DD + k0] = tohalf8(vs);
}

// Wd [1024][512] fp32 -> g_bw [512][1024] fp16 (transposed)
__global__ __launch_bounds__(256) void split_w(const float* __restrict__ in) {
    size_t i = (size_t)blockIdx.x * 256 + threadIdx.x;   // OO * UU/8
    int n = (int)(i & (OO - 1));
    int k0 = (int)(i >> 9) * 8;
    float vs[8];
#pragma unroll
    for (int j = 0; j < 8; j++)
        vs[j] = in[(size_t)(k0 + j) * OO + n];
    *(uint4*)&g_bw[(size_t)n * UU + k0] = tohalf8(vs);
}

// ---------------- mma.sync fp16 GEMM (128x256 tile, warp 64x64) -------------
#define GEM_BUF 49152
#define MMASM (2 * GEM_BUF)

__global__ __launch_bounds__(256, 1) void mma_gemm(
    const __half* __restrict__ A2, const __half* __restrict__ B2,
    const float* __restrict__ bias, float* __restrict__ C, int K2, int N) {
    extern __shared__ char smc[];
    const uint32_t sbase = (uint32_t)__cvta_generic_to_shared(smc);
    const int tid = threadIdx.x;
    const int wid = tid >> 5, lid = tid & 31;
    const int n0 = blockIdx.x * 256;
    const int m0 = blockIdx.y * 128;
    const int wm = (wid & 1) * 64;
    const int wn = (wid >> 1) * 64;
    const int nch = K2 / 64;

    float d[4][8][4];
#pragma unroll
    for (int i = 0; i < 4; i++)
#pragma unroll
        for (int j = 0; j < 8; j++)
#pragma unroll
            for (int q = 0; q < 4; q++) d[i][j][q] = 0.0f;

    auto load_chunk = [&](int buf, int k0) {
        uint32_t ab = sbase + buf * GEM_BUF;
        uint32_t bb = ab + 16384;
#pragma unroll
        for (int i = 0; i < 4; i++) {           // A: 128 rows x 64k
            int e = tid + i * 256;
            int rr = e >> 3, c8 = e & 7;
            uint32_t off = swz((uint32_t)(rr * 128 + c8 * 16));
            cp16s(ab + off, A2 + (size_t)(m0 + rr) * K2 + k0 + c8 * 8);
        }
#pragma unroll
        for (int i = 0; i < 8; i++) {           // B: 256 rows x 64k
            int e = tid + i * 256;
            int rr = e >> 3, c8 = e & 7;
            uint32_t off = swz((uint32_t)(rr * 128 + c8 * 16));
            cp16s(bb + off, B2 + (size_t)(n0 + rr) * K2 + k0 + c8 * 8);
        }
    };

    load_chunk(0, 0);
    CP_COMMIT();

    int buf = 0;
    for (int c = 0; c < nch; c++) {
        if (c + 1 < nch) {
            load_chunk(buf ^ 1, (c + 1) * 64);
            CP_COMMIT();
            CP_WAIT(1);
        } else {
            CP_WAIT(0);
        }
        __syncthreads();

        const uint32_t ab = sbase + buf * GEM_BUF;
        const uint32_t bb = ab + 16384;
#pragma unroll
        for (int kk = 0; kk < 64; kk += 16) {
            uint32_t af[4][4];
#pragma unroll
            for (int mi = 0; mi < 4; mi++) {
                uint32_t off = (uint32_t)((wm + mi * 16 + (lid & 15)) * 128
                                          + kk * 2 + (lid >> 4) * 16);
                ldsm_x4(af[mi][0], af[mi][1], af[mi][2], af[mi][3], ab + swz(off));
            }
            uint32_t bf_[8][2];
#pragma unroll
            for (int ni = 0; ni < 4; ni++) {
                int sub = lid >> 3;
                uint32_t off = (uint32_t)((wn + ni * 16 + ((sub >> 1) & 1) * 8
                                           + (lid & 7)) * 128
                                          + kk * 2 + (sub & 1) * 16);
                ldsm_x4(bf_[ni * 2][0], bf_[ni * 2][1],
                        bf_[ni * 2 + 1][0], bf_[ni * 2 + 1][1], bb + swz(off));
            }
#pragma unroll
            for (int mi = 0; mi < 4; mi++)
#pragma unroll
                for (int nf = 0; nf < 8; nf++)
                    mma16816h(d[mi][nf], af[mi], bf_[nf]);
        }
        __syncthreads();
        buf ^= 1;
    }

    const int lr = lid >> 2;
    const int lc = (lid & 3) * 2;
#pragma unroll
    for (int mi = 0; mi < 4; mi++) {
#pragma unroll
        for (int nf = 0; nf < 8; nf++) {
            int col = n0 + wn + nf * 8 + lc;
            float b0 = bias[col], b1 = bias[col + 1];
            int row0 = m0 + wm + mi * 16 + lr;
            float2 v0 = make_float2(d[mi][nf][0] + b0, d[mi][nf][1] + b1);
            float2 v1 = make_float2(d[mi][nf][2] + b0, d[mi][nf][3] + b1);
            *(float2*)&C[(size_t)row0 * N + col] = v0;
            *(float2*)&C[(size_t)(row0 + 8) * N + col] = v1;
        }
    }
}

// ---------------- projection GEMM (128x256 tile): out = hs @ Wd + bd ---------
__global__ __launch_bounds__(256, 1) void proj_gemm(
    const __half* __restrict__ hf, const __half* __restrict__ B2,
    const float* __restrict__ bias, float* __restrict__ C) {
    extern __shared__ char smc[];
    const uint32_t sbase = (uint32_t)__cvta_generic_to_shared(smc);
    const int tid = threadIdx.x;
    const int wid = tid >> 5, lid = tid & 31;
    const int n0 = blockIdx.x * 256;
    const int m0 = blockIdx.y * 128;
    const int wm = (wid & 1) * 64;
    const int wn = (wid >> 1) * 64;
    const int nch = 16;   // 1024 / 64

    float d[4][8][4];
#pragma unroll
    for (int i = 0; i < 4; i++)
#pragma unroll
        for (int j = 0; j < 8; j++)
#pragma unroll
            for (int q = 0; q < 4; q++) d[i][j][q] = 0.0f;

    auto load_chunk = [&](int buf, int ck) {
        uint32_t ab = sbase + buf * GEM_BUF;
        uint32_t bb = ab + 16384;
        const int kcol = ck * 64;
#pragma unroll
        for (int i = 0; i < 4; i++) {
            int e = tid + i * 256;
            int rr = e >> 3, c8 = e & 7;
            uint32_t off = swz((uint32_t)(rr * 128 + c8 * 16));
            int m = m0 + rr;
            int b = m >> 9, t = m & 511;           // m = b*TT + t
            cp16s(ab + off, hf + ((size_t)(t + 1) * BB + b) * UU + kcol + c8 * 8);
        }
#pragma unroll
        for (int i = 0; i < 8; i++) {
            int e = tid + i * 256;
            int rr = e >> 3, c8 = e & 7;
            uint32_t off = swz((uint32_t)(rr * 128 + c8 * 16));
            cp16s(bb + off, B2 + (size_t)(n0 + rr) * UU + kcol + c8 * 8);
        }
    };

    load_chunk(0, 0);
    CP_COMMIT();

    int buf = 0;
    for (int c = 0; c < nch; c++) {
        if (c + 1 < nch) {
            load_chunk(buf ^ 1, c + 1);
            CP_COMMIT();
            CP_WAIT(1);
        } else {
            CP_WAIT(0);
        }
        __syncthreads();

        const uint32_t ab = sbase + buf * GEM_BUF;
        const uint32_t bb = ab + 16384;
#pragma unroll
        for (int kk = 0; kk < 64; kk += 16) {
            uint32_t af[4][4];
#pragma unroll
            for (int mi = 0; mi < 4; mi++) {
                uint32_t off = (uint32_t)((wm + mi * 16 + (lid & 15)) * 128
                                          + kk * 2 + (lid >> 4) * 16);
                ldsm_x4(af[mi][0], af[mi][1], af[mi][2], af[mi][3], ab + swz(off));
            }
            uint32_t bf_[8][2];
#pragma unroll
            for (int ni = 0; ni < 4; ni++) {
                int sub = lid >> 3;
                uint32_t off = (uint32_t)((wn + ni * 16 + ((sub >> 1) & 1) * 8
                                           + (lid & 7)) * 128
                                          + kk * 2 + (sub & 1) * 16);
                ldsm_x4(bf_[ni * 2][0], bf_[ni * 2][1],
                        bf_[ni * 2 + 1][0], bf_[ni * 2 + 1][1], bb + swz(off));
            }
#pragma unroll
            for (int mi = 0; mi < 4; mi++)
#pragma unroll
                for (int nf = 0; nf < 8; nf++)
                    mma16816h(d[mi][nf], af[mi], bf_[nf]);
        }
        __syncthreads();
        buf ^= 1;
    }

    const int lr = lid >> 2;
    const int lc = (lid & 3) * 2;
#pragma unroll
    for (int mi = 0; mi < 4; mi++) {
#pragma unroll
        for (int nf = 0; nf < 8; nf++) {
            int col = n0 + wn + nf * 8 + lc;
            float b0 = bias[col], b1 = bias[col + 1];
            int row0 = m0 + wm + mi * 16 + lr;
            float2 v0 = make_float2(d[mi][nf][0] + b0, d[mi][nf][1] + b1);
            float2 v1 = make_float2(d[mi][nf][2] + b0, d[mi][nf][3] + b1);
            *(float2*)&C[(size_t)row0 * OO + col] = v0;
            *(float2*)&C[(size_t)(row0 + 8) * OO + col] = v1;
        }
    }
}

// ---------------- persistent MMA LSTM scan (R15 shape, 3-buffer A pipeline) --
// 128 CTAs, 256 threads. CTA bx owns hidden cols [8bx,8bx+8) x 4 gates (N=32).
// R resident in smem fp16 (64 KB). z = xz + hq@Rh. A stream: 8 chunks of
// K=128, THREE buffers with issue-before-wait (load c+2 issued, then WAIT(2)
// drains chunk c) — 2 chunks of lookahead over the post-barrier cold start.
// Arithmetic bit-identical to R15.
#define SC_RH 0
#define SC_A  65536
#define SCANSM (SC_A + 3 * 32768)   // 163840

__global__ __launch_bounds__(256, 1) void lstm_scan_mma(
    const float* __restrict__ R, const float* __restrict__ c0in) {
    extern __shared__ char smc[];
    const uint32_t sb = (uint32_t)__cvta_generic_to_shared(smc);
    const int tid = threadIdx.x;
    const int wid = tid >> 5, lid = tid & 31;
    const int u0 = blockIdx.x * 8;
    const int wm = wid * 16;

    // ---- one-time: R slice -> smem fp16, swizzled 64-col chunks ----
    for (int e = tid; e < 32 * UU; e += 256) {
        int n = e & 31, k = e >> 5;
        int gate = n >> 3, j = n & 7;
        float v = R[(size_t)k * GG + gate * UU + u0 + j];
        uint32_t off = (uint32_t)((k >> 6) * 4096) + swz((uint32_t)(n * 128 + (k & 63) * 2));
        *(__half*)(smc + SC_RH + off) = __float2half_rn(v);
    }

    const int lr = lid >> 2, lc = (lid & 3) * 2;
    const int b1 = wm + lr, b2 = b1 + 8;
    const int bs_[4] = {b1, b1, b2, b2};
    const int uj_[4] = {lc, lc + 1, lc, lc + 1};

    float creg[4];
#pragma unroll
    for (int i = 0; i < 4; i++)
        creg[i] = c0in[(size_t)bs_[i] * UU + u0 + uj_[i]];

    __syncthreads();

    for (int t = 0; t < TT; t++) {
        const __half* abase = g_hf + (size_t)t * BB * UU;   // h_{t-1} (slot t)

        // one chunk = K cols [ck*128, ck*128+128): two 16KB sub-tiles
        auto loadA = [&](int buf, int ck) {
            uint32_t ah = sb + SC_A + buf * 32768;
#pragma unroll
            for (int i = 0; i < 8; i++) {
                int e = tid + i * 256;              // 0..2047
                int s = e >> 10;                    // sub-tile 0/1
                int e2 = e & 1023;
                int rr = e2 >> 3, c8 = e2 & 7;
                uint32_t off = (uint32_t)(s * 16384)
                             + swz((uint32_t)(rr * 128 + c8 * 16));
                cp16s(ah + off,
                      abase + (size_t)rr * UU + ck * 128 + s * 64 + c8 * 8);
            }
        };

        loadA(0, 0);
        CP_COMMIT();
        loadA(1, 1);
        CP_COMMIT();

        float xzv[4][4];
#pragma unroll
        for (int i = 0; i < 4; i++) {
            const float* p = &g_xz[((size_t)bs_[i] * TT + t) * GG + u0 + uj_[i]];
#pragma unroll
            for (int g = 0; g < 4; g++) xzv[i][g] = p[(size_t)g * UU];
        }

        float d[4][4];
#pragma unroll
        for (int f = 0; f < 4; f++)
#pragma unroll
            for (int q = 0; q < 4; q++) d[f][q] = 0.0f;

        int buf = 0;
        for (int ck = 0; ck < 8; ck++) {
            // issue-before-wait, depth-3
            if (ck + 2 < 8) {
                int bn = buf + 2; if (bn >= 3) bn -= 3;
                loadA(bn, ck + 2);
                CP_COMMIT();
                CP_WAIT(2);
            } else if (ck + 1 < 8) {
                CP_WAIT(1);
            } else {
                CP_WAIT(0);
            }
            __syncthreads();

            const uint32_t ah = sb + SC_A + buf * 32768;
#pragma unroll
            for (int s = 0; s < 2; s++) {
                const uint32_t ahs = ah + s * 16384;
                const int rck = ck * 2 + s;
                const uint32_t rh = sb + SC_RH + rck * 4096;
#pragma unroll
                for (int kk = 0; kk < 64; kk += 16) {
                    uint32_t offA = swz((uint32_t)((wm + (lid & 15)) * 128
                                                   + kk * 2 + (lid >> 4) * 16));
                    uint32_t af[4];
                    ldsm_x4(af[0], af[1], af[2], af[3], ahs + offA);

                    uint32_t bh[4][2];
#pragma unroll
                    for (int ni = 0; ni < 2; ni++) {
                        int sub = lid >> 3;
                        uint32_t offB = swz((uint32_t)((ni * 16 + ((sub >> 1) & 1) * 8
                                                        + (lid & 7)) * 128
                                                       + kk * 2 + (sub & 1) * 16));
                        ldsm_x4(bh[ni * 2][0], bh[ni * 2][1],
                                bh[ni * 2 + 1][0], bh[ni * 2 + 1][1], rh + offB);
                    }
#pragma unroll
                    for (int f = 0; f < 4; f++)
                        mma16816h(d[f], af, bh[f]);
                }
            }
            __syncthreads();
            buf = (buf == 2) ? 0 : buf + 1;
        }

        float hn[4];
#pragma unroll
        for (int i = 0; i < 4; i++) {
            float zi = d[0][i] + xzv[i][0];
            float zf = d[1][i] + xzv[i][1];
            float zg = d[2][i] + xzv[i][2];
            float zo = d[3][i] + xzv[i][3];
            float ig = sigmoidf_(zi);
            float fg = sigmoidf_(zf);
            float og = sigmoidf_(zo);
            float gg = tanhf(zg);
            float cn = fg * creg[i] + ig * gg;
            creg[i] = cn;
            hn[i] = og * tanhf(cn);
        }

        // write h_t as fp16 (scan A for t+1 AND projection A)
#pragma unroll
        for (int pp = 0; pp < 2; pp++) {
            int b = pp ? b2 : b1;
            __half q0 = __float2half_rn(hn[pp * 2]);
            __half q1 = __float2half_rn(hn[pp * 2 + 1]);
            *(uint32_t*)&g_hf[((size_t)(t + 1) * BB + b) * UU + u0 + lc] =
                packhf(q0, q1);
        }

        // grid barrier
        __syncthreads();
        if (tid == 0) {
            __threadfence();
            atomicAdd(&g_bar, 1u);
            unsigned target = (unsigned)(t + 1) * NBLK;
            unsigned v;
            do {
                asm volatile("ld.global.acquire.gpu.u32 %0, [%1];"
                             : "=r"(v) : "l"(&g_bar) : "memory");
                if (v < target) __nanosleep(32);
            } while (v < target);
        }
        __syncthreads();
    }
}

// ---------------- host launcher --------------------------------------------
extern "C" void kernel_launch(void* const* d_in, const int* in_sizes, int n_in,
                              void* d_out, int out_size) {
    const float* x      = (const float*)d_in[0];
    const float* h0     = (const float*)d_in[1];
    const float* c0in   = (const float*)d_in[2];
    const float* kernel = (const float*)d_in[3];
    const float* rec    = (const float*)d_in[4];
    const float* bias   = (const float*)d_in[5];
    const float* Wd     = (const float*)d_in[6];
    const float* bd     = (const float*)d_in[7];
    float* out = (float*)d_out;

    void *p_xz, *p_ax, *p_bk, *p_bw, *p_hf;
    cudaGetSymbolAddress(&p_xz, g_xz);
    cudaGetSymbolAddress(&p_ax, g_ax);
    cudaGetSymbolAddress(&p_bk, g_bk);
    cudaGetSymbolAddress(&p_bw, g_bw);
    cudaGetSymbolAddress(&p_hf, g_hf);

    static bool attr_done = false;
    if (!attr_done) {
        cudaFuncSetAttribute(lstm_scan_mma,
                             cudaFuncAttributeMaxDynamicSharedMemorySize, SCANSM);
        cudaFuncSetAttribute(mma_gemm,
                             cudaFuncAttributeMaxDynamicSharedMemorySize, MMASM);
        cudaFuncSetAttribute(proj_gemm,
                             cudaFuncAttributeMaxDynamicSharedMemorySize, MMASM);
        attr_done = true;
    }

    // 1) state init + operand converts (vectorized)
    init_state<<<(BB * UU / 8) / 256, 256>>>(h0);
    split_x<<<(int)((size_t)MM * DD / 8 / 256), 256>>>(x);
    split_k<<<(int)((size_t)DD * GG / 8 / 256), 256>>>(kernel);
    split_w<<<(int)((size_t)UU * OO / 8 / 256), 256>>>(Wd);

    // 2) xz = x @ kernel + bias  (fp16 1-term; M=65536, N=4096, K=512)
    {
        dim3 grid(GG / 256, MM / 128);
        mma_gemm<<<grid, 256, MMASM>>>((const __half*)p_ax, (const __half*)p_bk,
                                       bias, (float*)p_xz, DD, GG);
    }

    // 3) persistent MMA LSTM scan (R15 shape, 3-buffer pipeline, writes g_hf)
    lstm_scan_mma<<<NBLK, 256, SCANSM>>>(rec, c0in);

    // 4) out = hs @ Wd + bd  (fp16 1-term from g_hf; M=65536, N=512, K=1024)
    {
        dim3 grid(OO / 256, MM / 128);
        proj_gemm<<<grid, 256, MMASM>>>((const __half*)p_hf, (const __half*)p_bw,
                                        bd, out);
    }
}